// round 15
// baseline (speedup 1.0000x reference)
#include <cuda_runtime.h>
#include <cuda_fp16.h>
#include <cstdint>
#include <cstddef>

// ---------------------------------------------------------------------------
// Out[b] = [W_e | W_h](128x256) @ [e_vw[b]; h_w[b]](256x512) + (b_e + b_h)
// B=1024, M=128, K=256, N=512.
// Persistent CTA (NB=4 batches), whole prepacked-fp16 W resident in smem
// (pitch 264 halves -> conflict-free ldmatrix).
// B path (NEW): LDG.128 fp32 one chunk ahead -> pack fp16 in regs -> STS.64
// into 2-stage fp16 buffer (pitch 72 halves) -> ldmatrix.x4.trans fragments.
// Replaces 16 scalar LDS + 8 packs per warp per chunk with 2 ldmatrix ops.
// Warp grid 4m x 2n (tile 32x32), direct-STG epilogue. 2 CTAs/SM.
// ---------------------------------------------------------------------------

#define A_PITCH_H     264                     // halves per W row (528 B)
#define A_TOTAL_BYTES (128 * A_PITCH_H * 2)   // 67584
#define B_PITCH_H     72                      // halves per B row (144 B)
#define B_STAGE_BYTES (32 * B_PITCH_H * 2)    // 4608
#define SMEM_TOTAL    (A_TOTAL_BYTES + 2 * B_STAGE_BYTES)   // 76800
#define NB            4
#define NCHUNK        (NB * 8)                // 32 K-chunks

__device__ __half g_W[128 * 256];     // [m][k] fp16, k-contiguous
__device__ float  g_bias[128];

__global__ __launch_bounds__(256)
void prep_kernel(const float* __restrict__ W_e, const float* __restrict__ W_h,
                 const float* __restrict__ b_e, const float* __restrict__ b_h) {
    const int idx = blockIdx.x * 256 + threadIdx.x;     // 0..32767
    const int m = idx >> 8, k = idx & 255;
    const float v = (k < 128) ? W_e[m * 128 + k] : W_h[m * 128 + (k - 128)];
    g_W[idx] = __float2half(v);
    if (idx < 128) g_bias[idx] = b_e[idx] + b_h[idx];
}

static __device__ __forceinline__ uint32_t smem_u32(const void* p) {
    uint32_t a;
    asm("{ .reg .u64 t; cvta.to.shared.u64 t, %1; cvt.u32.u64 %0, t; }"
        : "=r"(a) : "l"(p));
    return a;
}
static __device__ __forceinline__ void ldmx4(uint32_t* r, uint32_t addr) {
    asm volatile("ldmatrix.sync.aligned.m8n8.x4.shared.b16 {%0,%1,%2,%3}, [%4];"
                 : "=r"(r[0]), "=r"(r[1]), "=r"(r[2]), "=r"(r[3]) : "r"(addr));
}
static __device__ __forceinline__ void ldmx4t(uint32_t* r, uint32_t addr) {
    asm volatile("ldmatrix.sync.aligned.m8n8.x4.trans.shared.b16 {%0,%1,%2,%3}, [%4];"
                 : "=r"(r[0]), "=r"(r[1]), "=r"(r[2]), "=r"(r[3]) : "r"(addr));
}
static __device__ __forceinline__ void mma16816(float* d, const uint32_t* a,
                                                uint32_t b0, uint32_t b1) {
    asm volatile(
        "mma.sync.aligned.m16n8k16.row.col.f32.f16.f16.f32 "
        "{%0,%1,%2,%3}, {%4,%5,%6,%7}, {%8,%9}, {%0,%1,%2,%3};"
        : "+f"(d[0]), "+f"(d[1]), "+f"(d[2]), "+f"(d[3])
        : "r"(a[0]), "r"(a[1]), "r"(a[2]), "r"(a[3]), "r"(b0), "r"(b1));
}
static __device__ __forceinline__ uint32_t packh2(float x, float y) {
    __half2 h = __floats2half2_rn(x, y);
    return *reinterpret_cast<uint32_t*>(&h);
}
static __device__ __forceinline__ void cp16(uint32_t smem_addr, const void* g) {
    asm volatile("cp.async.cg.shared.global [%0], [%1], 16;"
                 :: "r"(smem_addr), "l"(g) : "memory");
}
static __device__ __forceinline__ void cp_commit() {
    asm volatile("cp.async.commit_group;" ::: "memory");
}
template <int N>
static __device__ __forceinline__ void cp_wait() {
    asm volatile("cp.async.wait_group %0;" :: "n"(N) : "memory");
}

__global__ __launch_bounds__(256, 2)
void msg_kernel(const float* __restrict__ h_w, const float* __restrict__ e_vw,
                float* __restrict__ out) {
    extern __shared__ char smem[];
    __shared__ float sbias[128];

    const int tid  = threadIdx.x;
    const int lane = tid & 31;
    const int wid  = tid >> 5;
    const int b0   = blockIdx.y * NB;          // first batch of this CTA
    const int n0   = blockIdx.x << 6;          // 0..448 step 64

    if (tid < 128) sbias[tid] = g_bias[tid];

    const uint32_t sA = smem_u32(smem);
    const uint32_t sB = sA + A_TOTAL_BYTES;    // 2 fp16 B stages

    // -------- A prologue: whole prepacked W -> smem (one cp.async group) ----
    #pragma unroll
    for (int t = 0; t < 16; t++) {
        const int idx = tid + (t << 8);        // 4096 x 16B
        const int m = idx >> 5, q = idx & 31;
        cp16(sA + (uint32_t)(m * 528 + q * 16), g_W + m * 256 + q * 8);
    }
    cp_commit();

    // B staging: per chunk each thread owns 8 floats -> 4 packed u32.
    const int bk  = tid >> 4;                  // k row 0..15 (x2 passes)
    const int bn4 = (tid & 15) << 2;           // n 0..60 step 4
    uint32_t pB[4];

    auto ldg_B = [&](int ci) {
        const int bat = b0 + (ci >> 3);
        const int k0  = (ci & 7) << 5;
        const float* X = (k0 < 128)
            ? (e_vw + (size_t)bat * 65536 + n0 + (size_t)k0 * 512)
            : (h_w  + (size_t)bat * 65536 + n0 + (size_t)(k0 - 128) * 512);
        #pragma unroll
        for (int t = 0; t < 2; t++) {
            const int k = bk + (t << 4);
            float4 v = *reinterpret_cast<const float4*>(X + (size_t)k * 512 + bn4);
            pB[2 * t]     = packh2(v.x, v.y);
            pB[2 * t + 1] = packh2(v.z, v.w);
        }
    };
    auto sts_B = [&](int buf) {
        const uint32_t bst = sB + (uint32_t)buf * B_STAGE_BYTES;
        #pragma unroll
        for (int t = 0; t < 2; t++) {
            const int k = bk + (t << 4);
            // halves addr: k*72 + bn4  -> bytes 144k + 2*bn4 (8B aligned)
            *reinterpret_cast<uint2*>(
                smem + (bst - sA) + (uint32_t)(k * 144 + bn4 * 2)) =
                make_uint2(pB[2 * t], pB[2 * t + 1]);
        }
    };

    // Warp grid: 4m x 2n, warp tile 32m x 32n
    const int wm = (wid >> 1) << 5;            // 0,32,64,96
    const int wn = (wid & 1) << 5;             // 0,32
    float acc[2][4][4];
    #pragma unroll
    for (int i = 0; i < 2; i++)
        #pragma unroll
        for (int j = 0; j < 4; j++)
            #pragma unroll
            for (int r = 0; r < 4; r++) acc[i][j][r] = 0.f;

    const int j8  = lane & 7;
    const int sel = lane >> 3;
    const int r0  = lane >> 2;
    const int c0  = (lane & 3) << 1;

    // A ldmatrix bases: row = wm + 16i + 8*(sel&1) + j8, col-half = (sel>>1)*8
    uint32_t aRow[2];
    #pragma unroll
    for (int i = 0; i < 2; i++)
        aRow[i] = sA + (uint32_t)((wm + (i << 4) + ((sel & 1) << 3) + j8) * 528
                                  + ((sel >> 1) << 3) * 2);
    // B ldmatrix.trans base: row kr = (sel&1)*8 + j8 (+kk), col nc = wn + g*16 + (sel>>1)*8
    const uint32_t bRowBase =
        (uint32_t)((((sel & 1) << 3) + j8) * B_PITCH_H
                   + wn + ((sel >> 1) << 3)) * 2;

    // -------- prologue --------
    ldg_B(0);
    cp_wait<0>();                              // A resident
    __syncthreads();
    sts_B(0);
    ldg_B(1);
    __syncthreads();                           // stage 0 visible

    // -------- mainloop: 32 chunks, one barrier per chunk --------
    // WAR: barrier at end of iter ci proves compute(ci) done; sts_B(ci+2)
    // (next iter) writes stage ci&1 only after that barrier. RAW: sts_B(ci+1)
    // in iter ci is published by the same barrier before compute(ci+1).
    for (int ci = 0; ci < NCHUNK; ci++) {
        const uint32_t aK = (uint32_t)((ci & 7) << 6);          // chunk A bytes
        const uint32_t bSt = sB + (uint32_t)(ci & 1) * B_STAGE_BYTES;

        #pragma unroll
        for (int ks = 0; ks < 2; ks++) {
            const int kk = ks << 4;
            uint32_t afr[2][4];
            #pragma unroll
            for (int i = 0; i < 2; i++)
                ldmx4(afr[i], aRow[i] + aK + (uint32_t)(kk * 2));
            uint32_t bfr[2][4];
            #pragma unroll
            for (int g = 0; g < 2; g++)
                ldmx4t(bfr[g], bSt + bRowBase
                               + (uint32_t)(kk * B_PITCH_H + (g << 4)) * 2);
            #pragma unroll
            for (int i = 0; i < 2; i++)
                #pragma unroll
                for (int j = 0; j < 4; j++)
                    mma16816(acc[i][j], afr[i], bfr[j >> 1][(j & 1) << 1],
                             bfr[j >> 1][((j & 1) << 1) + 1]);
        }

        if (ci + 1 < NCHUNK) sts_B((ci + 1) & 1);   // stage disjoint from ci&1
        if (ci + 2 < NCHUNK) ldg_B(ci + 2);         // refill staging regs

        // -------- per-batch epilogue: direct STG from accumulators --------
        if ((ci & 7) == 7) {
            const int bat = b0 + (ci >> 3);
            float* outp = out + (size_t)bat * 65536 + n0;
            #pragma unroll
            for (int i = 0; i < 2; i++) {
                const int r  = wm + (i << 4) + r0;
                const float bias0 = sbias[r];
                const float bias1 = sbias[r + 8];
                #pragma unroll
                for (int j = 0; j < 4; j++) {
                    const int c = wn + (j << 3) + c0;
                    float2 v0 = make_float2(acc[i][j][0] + bias0,
                                            acc[i][j][1] + bias0);
                    float2 v1 = make_float2(acc[i][j][2] + bias1,
                                            acc[i][j][3] + bias1);
                    *reinterpret_cast<float2*>(outp + (size_t)r * 512 + c) = v0;
                    *reinterpret_cast<float2*>(outp + (size_t)(r + 8) * 512 + c) = v1;
                    acc[i][j][0] = 0.f; acc[i][j][1] = 0.f;
                    acc[i][j][2] = 0.f; acc[i][j][3] = 0.f;
                }
            }
        }
        __syncthreads();
    }
}

extern "C" void kernel_launch(void* const* d_in, const int* in_sizes, int n_in,
                              void* d_out, int out_size) {
    // metadata order: h_v(unused), h_w, e_vw, W_e, b_e, W_h, b_h
    const float* h_w  = (const float*)d_in[1];
    const float* e_vw = (const float*)d_in[2];
    const float* W_e  = (const float*)d_in[3];
    const float* b_e  = (const float*)d_in[4];
    const float* W_h  = (const float*)d_in[5];
    const float* b_h  = (const float*)d_in[6];
    float* out = (float*)d_out;

    prep_kernel<<<128, 256>>>(W_e, W_h, b_e, b_h);

    cudaFuncSetAttribute(msg_kernel, cudaFuncAttributeMaxDynamicSharedMemorySize,
                         SMEM_TOTAL);
    dim3 grid(8, 256);
    msg_kernel<<<grid, 256, SMEM_TOTAL>>>(h_w, e_vw, out);
}